// round 3
// baseline (speedup 1.0000x reference)
#include <cuda_runtime.h>
#include <math.h>

#define NROWS 65536
#define D 512
#define H 10
#define G4 40
#define MAXCELLS (4 * NROWS + 16)
#define CSTRIDE 44   // floats per cell record (11 float4)

// ---------------- scratch (static device globals; no allocation) ----------------
__device__ float  g_y[NROWS * H];                 // layer-1 pre-BN activations
__device__ __align__(16) float4 g_cells4[MAXCELLS * (CSTRIDE / 4)]; // flat cell list
__device__ int    g_prefzp[NROWS];                // exclusive prefix of zp
__device__ int    g_ncells;
__device__ float  g_outs[NROWS * H];              // scan outputs (ht)
__device__ double g_s1[H], g_sq1[H];              // BN1 sums
__device__ float  g_scale1[H], g_shift1[H];
__device__ double g_s2[2 * H];                    // BN2 sums
__device__ float  g_alpha[H];
__device__ float  g_cst[1];

// ---------------- f32x2 packed helpers ----------------
typedef unsigned long long ull;
__device__ __forceinline__ ull pk2(float lo, float hi) {
    ull r; asm("mov.b64 %0, {%1, %2};" : "=l"(r) : "f"(lo), "f"(hi)); return r;
}
__device__ __forceinline__ void upk2(ull v, float& lo, float& hi) {
    asm("mov.b64 {%0, %1}, %2;" : "=f"(lo), "=f"(hi) : "l"(v));
}
__device__ __forceinline__ ull fma2(ull a, ull b, ull c) {
    ull d; asm("fma.rn.f32x2 %0, %1, %2, %3;" : "=l"(d) : "l"(a), "l"(b), "l"(c)); return d;
}
__device__ __forceinline__ ull add2(ull a, ull b) {
    ull d; asm("add.rn.f32x2 %0, %1, %2;" : "=l"(d) : "l"(a), "l"(b)); return d;
}
__device__ __forceinline__ float tanhapx(float x) {
    float y; asm("tanh.approx.f32 %0, %1;" : "=f"(y) : "f"(x)); return y;
}

// ---------------- init ----------------
__global__ void k_init() {
    int t = threadIdx.x;
    if (t < H)     { g_s1[t] = 0.0; g_sq1[t] = 0.0; }
    if (t < 2 * H) { g_s2[t] = 0.0; }
}

// ---------------- kernel A: y = x @ W1^T + b1, accumulate BN1 sums ----------------
__global__ void k_proj(const float* __restrict__ x,
                       const float* __restrict__ W1,
                       const float* __restrict__ b1) {
    int gtid  = blockIdx.x * blockDim.x + threadIdx.x;
    int w     = gtid >> 5;
    int lane  = threadIdx.x & 31;
    int nwarp = (gridDim.x * blockDim.x) >> 5;

    double ls[H], lq[H];
#pragma unroll
    for (int j = 0; j < H; j++) { ls[j] = 0.0; lq[j] = 0.0; }

    const float4* x4  = reinterpret_cast<const float4*>(x);
    const float4* W14 = reinterpret_cast<const float4*>(W1);

    for (int n = w; n < NROWS; n += nwarp) {
        float acc[H];
#pragma unroll
        for (int j = 0; j < H; j++) acc[j] = 0.f;
        const float4* xr = x4 + (size_t)n * (D / 4);
#pragma unroll
        for (int it = 0; it < D / 4 / 32; it++) {
            float4 xv = __ldg(xr + lane + 32 * it);
#pragma unroll
            for (int j = 0; j < H; j++) {
                float4 wv = __ldg(W14 + j * (D / 4) + lane + 32 * it);
                acc[j] += xv.x * wv.x + xv.y * wv.y + xv.z * wv.z + xv.w * wv.w;
            }
        }
#pragma unroll
        for (int j = 0; j < H; j++) {
#pragma unroll
            for (int off = 16; off; off >>= 1)
                acc[j] += __shfl_xor_sync(0xffffffffu, acc[j], off);
        }
        if (lane == 0) {
#pragma unroll
            for (int j = 0; j < H; j++) {
                float yv = acc[j] + __ldg(b1 + j);
                g_y[n * H + j] = yv;
                ls[j] += (double)yv;
                lq[j] += (double)yv * (double)yv;
            }
        }
    }
    if (lane == 0) {
#pragma unroll
        for (int j = 0; j < H; j++) {
            atomicAdd(&g_s1[j], ls[j]);
            atomicAdd(&g_sq1[j], lq[j]);
        }
    }
}

// ---------------- BN1 affine params ----------------
__global__ void k_bnparams(const float* __restrict__ g1, const float* __restrict__ be1) {
    int t = threadIdx.x;
    if (t < H) {
        double m   = g_s1[t] / (double)NROWS;
        double var = g_sq1[t] / (double)NROWS - m * m;
        float inv  = (float)(1.0 / sqrt(var + 1e-5));
        float sc   = inv * __ldg(g1 + t);
        g_scale1[t] = sc;
        g_shift1[t] = __ldg(be1 + t) - (float)m * sc;
    }
}

// ---------------- prefix sum of zero_pad (single block) ----------------
__global__ void k_prefix(const int* __restrict__ zero_pad) {
    __shared__ int s[1024];
    int tid = threadIdx.x;
    int tsum = 0;
    for (int i = 0; i < NROWS / 1024; i++) {
        int z = __ldg(zero_pad + tid * (NROWS / 1024) + i);
        z = min(max(z, 0), 3);
        tsum += z;
    }
    s[tid] = tsum;
    __syncthreads();
    for (int off = 1; off < 1024; off <<= 1) {
        int v = (tid >= off) ? s[tid - off] : 0;
        __syncthreads();
        s[tid] += v;
        __syncthreads();
    }
    int run = s[tid] - tsum;   // exclusive
    for (int i = 0; i < NROWS / 1024; i++) {
        int t = tid * (NROWS / 1024) + i;
        int z = __ldg(zero_pad + t);
        z = min(max(z, 0), 3);
        g_prefzp[t] = run;
        run += z;
    }
    if (tid == 1023) g_ncells = NROWS + run;
}

// ---------------- build the flat cell list ----------------
__global__ void k_cells(const float* __restrict__ W_ih,
                        const float* __restrict__ b_ih, const float* __restrict__ b_hh,
                        const int* __restrict__ zero_pad, const int* __restrict__ broad_id) {
    __shared__ float sW[G4 * H], sb[G4], sb0[G4];
    for (int i = threadIdx.x; i < G4 * H; i += blockDim.x) sW[i] = __ldg(W_ih + i);
    for (int i = threadIdx.x; i < G4; i += blockDim.x) {
        float b = __ldg(b_ih + i) + __ldg(b_hh + i);
        sb[i] = b;
        sb0[i] = ((i / H) == 2) ? b : 0.5f * b;   // pre-scaled zero-cell gate bases
    }
    __syncthreads();

    int t = blockIdx.x * blockDim.x + threadIdx.x;
    if (t >= NROWS) return;

    float x1[H];
#pragma unroll
    for (int j = 0; j < H; j++)
        x1[j] = g_y[t * H + j] * g_scale1[j] + g_shift1[j];

    float u[G4];
#pragma unroll
    for (int r = 0; r < G4; r++) {
        float acc = sb[r];
#pragma unroll
        for (int j = 0; j < H; j++) acc += sW[r * H + j] * x1[j];
        if ((r / H) != 2) acc *= 0.5f;
        u[r] = acc;
    }

    int zp = __ldg(zero_pad + t);
    zp = min(max(zp, 0), 3);
    bool bnd = (t == NROWS - 1) || (__ldg(broad_id + t + 1) != __ldg(broad_id + t));
    float invc = 0.f;
    if (bnd) {
        int s = t, myid = __ldg(broad_id + t);
        while (s > 0 && __ldg(broad_id + s - 1) == myid) s--;
        invc = 1.0f / (float)(t - s + 1);
    }

    float* base = (float*)g_cells4 + (size_t)(t + g_prefzp[t]) * CSTRIDE;
    // zero cells
    for (int k = 0; k < zp; k++) {
        float* r = base + (size_t)k * CSTRIDE;
#pragma unroll
        for (int j = 0; j < H; j++) {
            r[4 * j]     = sb0[0 * H + j];
            r[4 * j + 1] = sb0[1 * H + j];
            r[4 * j + 2] = sb0[2 * H + j];
            r[4 * j + 3] = sb0[3 * H + j];
        }
        r[40] = 1.f;  r[41] = 0.f;  r[42] = 0.f;  r[43] = 0.f;
    }
    // input cell
    {
        float* r = base + (size_t)zp * CSTRIDE;
#pragma unroll
        for (int j = 0; j < H; j++) {
            r[4 * j]     = u[0 * H + j];
            r[4 * j + 1] = u[1 * H + j];
            r[4 * j + 2] = u[2 * H + j];
            r[4 * j + 3] = u[3 * H + j];
        }
        r[40] = 0.f;  r[41] = 1.f;  r[42] = invc;  r[43] = __int_as_float(t * H);
    }
    // tail pads (no-op cells) so the scan's unroll/prefetch can overrun safely
    if (t == 0) {
        int n = g_ncells;
        for (int p = 0; p < 12; p++) {
            float* r = (float*)g_cells4 + (size_t)(n + p) * CSTRIDE;
            for (int q = 0; q < CSTRIDE; q++) r[q] = 0.f;
        }
    }
}

// ---------------- the sequential scan: flat branchless cells, packed FMAs ----------------
__global__ void k_scan(const float* __restrict__ W_hh) {
    int j  = threadIdx.x;
    int lj = (j < H) ? j : 0;

    // packed weight rows: (i,f) and (g,o); 0.5 folded into sigmoid gates
    ull w2if[H], w2go[H];
#pragma unroll
    for (int k = 0; k < H; k++) {
        w2if[k] = pk2(0.5f * __ldg(W_hh + (0 * H + lj) * H + k),
                      0.5f * __ldg(W_hh + (1 * H + lj) * H + k));
        w2go[k] = pk2(       __ldg(W_hh + (2 * H + lj) * H + k),
                      0.5f * __ldg(W_hh + (3 * H + lj) * H + k));
    }

    ull h2[H];
#pragma unroll
    for (int k = 0; k < H; k++) h2[k] = 0ull;
    float h = 0.f, c = 0.f, sh = 0.f, sc = 0.f;

    int n  = g_ncells;
    int n4 = (n + 3) & ~3;

    // prefetch ring, depth 4, distance 3
    float4 U[4], M[4];
#pragma unroll
    for (int p = 0; p < 3; p++) {
        const float4* cp = g_cells4 + (size_t)p * (CSTRIDE / 4);
        U[p] = __ldg(cp + lj);
        M[p] = __ldg(cp + 10);
    }

    for (int i = 0; i < n4; i += 4) {
#pragma unroll
        for (int uu = 0; uu < 4; uu++) {
            int idx = i + uu;
            float4 uv = U[idx & 3];
            float4 mv = M[idx & 3];
            {   // prefetch idx+3
                const float4* cp = g_cells4 + (size_t)(idx + 3) * (CSTRIDE / 4);
                U[(idx + 3) & 3] = __ldg(cp + lj);
                M[(idx + 3) & 3] = __ldg(cp + 10);
            }

            // packed dots: (pi,pf) and (pg,po)
            ull aif0 = pk2(uv.x, uv.y), aif1 = 0ull;
            ull ago0 = pk2(uv.z, uv.w), ago1 = 0ull;
#pragma unroll
            for (int k = 0; k < H; k += 2) {
                aif0 = fma2(w2if[k],     h2[k],     aif0);
                aif1 = fma2(w2if[k + 1], h2[k + 1], aif1);
                ago0 = fma2(w2go[k],     h2[k],     ago0);
                ago1 = fma2(w2go[k + 1], h2[k + 1], ago1);
            }
            float pi, pf, pg, po;
            upk2(add2(aif0, aif1), pi, pf);
            upk2(add2(ago0, ago1), pg, po);

            float ig = fmaf(tanhapx(pi), 0.5f, 0.5f);
            float fg = fmaf(tanhapx(pf), 0.5f, 0.5f);
            float gg = tanhapx(pg);
            float og = fmaf(tanhapx(po), 0.5f, 0.5f);

            float ct2 = fmaf(fg, c, ig * gg);
            float ht  = og * tanhapx(ct2);

            bool adv = (mv.x != 0.f);
            bool inp = (mv.y != 0.f);
            bool bnd = (mv.z != 0.f);

            // sums (input cells only)
            float msk = mv.y;
            sh = fmaf(ht,  msk, sh);
            sc = fmaf(ct2, msk, sc);

            // carry update
            float hn = adv ? ht  : h;
            float cn = adv ? ct2 : c;
            float hb = sh * mv.z;
            float cb = sc * mv.z;
            h = bnd ? hb : hn;
            c = bnd ? cb : cn;
            sh = bnd ? 0.f : sh;
            sc = bnd ? 0.f : sc;

            if (inp && j < H)
                g_outs[__float_as_int(mv.w) + j] = ht;

            // broadcast h, duplicated into packed lanes
#pragma unroll
            for (int q = 0; q < H; q++) {
                float hq = __shfl_sync(0xffffffffu, h, q);
                h2[q] = pk2(hq, hq);
            }
        }
    }
}

// ---------------- BN2 sums over g_outs (parallel post-pass) ----------------
__global__ void k_stats() {
    int gtid  = blockIdx.x * blockDim.x + threadIdx.x;
    int w     = gtid >> 5;
    int lane  = threadIdx.x & 31;
    int nwarp = (gridDim.x * blockDim.x) >> 5;
    if (lane >= H) return;
    double s = 0.0, q = 0.0;
    for (int n = w; n < NROWS; n += nwarp) {
        double v = (double)g_outs[n * H + lane];
        s += v;
        q += v * v;
    }
    atomicAdd(&g_s2[lane], s);
    atomicAdd(&g_s2[H + lane], q);
}

// ---------------- fold BN2 + W2 + b2 ----------------
__global__ void k_post(const float* __restrict__ g2, const float* __restrict__ be2,
                       const float* __restrict__ W2, const float* __restrict__ b2) {
    if (threadIdx.x == 0) {
        float cst = __ldg(b2);
#pragma unroll
        for (int jj = 0; jj < H; jj++) {
            double m   = g_s2[jj] / (double)NROWS;
            double var = g_s2[H + jj] / (double)NROWS - m * m;
            float inv  = (float)(1.0 / sqrt(var + 1e-5));
            float a    = __ldg(W2 + jj) * __ldg(g2 + jj) * inv;
            g_alpha[jj] = a;
            cst += __ldg(W2 + jj) * __ldg(be2 + jj) - (float)m * a;
        }
        g_cst[0] = cst;
    }
}

// ---------------- out = tanh(outs . alpha + cst) ----------------
__global__ void k_final(float* __restrict__ out) {
    int n = blockIdx.x * blockDim.x + threadIdx.x;
    if (n >= NROWS) return;
    float acc = g_cst[0];
#pragma unroll
    for (int jj = 0; jj < H; jj++)
        acc += g_outs[n * H + jj] * g_alpha[jj];
    out[n] = tanhf(acc);
}

// ---------------- launch ----------------
extern "C" void kernel_launch(void* const* d_in, const int* in_sizes, int n_in,
                              void* d_out, int out_size) {
    const float* x        = (const float*)d_in[0];
    const int*   zero_pad = (const int*)d_in[1];
    const int*   broad_id = (const int*)d_in[2];
    const float* W1       = (const float*)d_in[3];
    const float* b1       = (const float*)d_in[4];
    const float* g1       = (const float*)d_in[5];
    const float* be1      = (const float*)d_in[6];
    const float* W_ih     = (const float*)d_in[7];
    const float* W_hh     = (const float*)d_in[8];
    const float* b_ih     = (const float*)d_in[9];
    const float* b_hh     = (const float*)d_in[10];
    const float* g2       = (const float*)d_in[11];
    const float* be2      = (const float*)d_in[12];
    const float* W2       = (const float*)d_in[13];
    const float* b2       = (const float*)d_in[14];
    float* out = (float*)d_out;

    k_init<<<1, 32>>>();
    k_proj<<<512, 256>>>(x, W1, b1);
    k_bnparams<<<1, 32>>>(g1, be1);
    k_prefix<<<1, 1024>>>(zero_pad);
    k_cells<<<NROWS / 128, 128>>>(W_ih, b_ih, b_hh, zero_pad, broad_id);
    k_scan<<<1, 32>>>(W_hh);
    k_stats<<<128, 256>>>();
    k_post<<<1, 32>>>(g2, be2, W2, b2);
    k_final<<<NROWS / 256, 256>>>(out);
}

// round 4
// speedup vs baseline: 55.8043x; 55.8043x over previous
#include <cuda_runtime.h>
#include <math.h>

#define NROWS 65536
#define D 512
#define H 10
#define G4 40
#define NCHUNK 512
#define WU 16          // warm-up groups per chunk

// ---------------- scratch (static device globals; no allocation) ----------------
__device__ float  g_y[NROWS * H];          // layer-1 pre-BN activations
__device__ float  g_u[(NROWS + 2) * G4];   // input-gate bases (i,f,o pre-scaled by 0.5)
__device__ float  g_outs[NROWS * H];       // scan outputs (ht)
__device__ int    g_meta[NROWS + 2];       // zp | (bnd<<8)
__device__ int    g_gstart[NROWS];         // first row of each group
__device__ int    g_ngroups;
__device__ double g_s1[H], g_sq1[H];       // BN1 sums
__device__ float  g_scale1[H], g_shift1[H];
__device__ float  g_bias0[G4];             // 0.5*(b_ih+b_hh) for i,f,o ; 1.0* for g
__device__ double g_s2[2 * H];             // BN2 sums
__device__ float  g_alpha[H];
__device__ float  g_cst[1];

// ---------------- init ----------------
__global__ void k_init() {
    int t = threadIdx.x;
    if (t < H)     { g_s1[t] = 0.0; g_sq1[t] = 0.0; }
    if (t < 2 * H) { g_s2[t] = 0.0; }
}

// ---------------- kernel A: y = x @ W1^T + b1, accumulate BN1 sums ----------------
__global__ void k_proj(const float* __restrict__ x,
                       const float* __restrict__ W1,
                       const float* __restrict__ b1) {
    int gtid  = blockIdx.x * blockDim.x + threadIdx.x;
    int w     = gtid >> 5;
    int lane  = threadIdx.x & 31;
    int nwarp = (gridDim.x * blockDim.x) >> 5;

    double ls[H], lq[H];
#pragma unroll
    for (int j = 0; j < H; j++) { ls[j] = 0.0; lq[j] = 0.0; }

    const float4* x4  = reinterpret_cast<const float4*>(x);
    const float4* W14 = reinterpret_cast<const float4*>(W1);

    for (int n = w; n < NROWS; n += nwarp) {
        float acc[H];
#pragma unroll
        for (int j = 0; j < H; j++) acc[j] = 0.f;
        const float4* xr = x4 + (size_t)n * (D / 4);
#pragma unroll
        for (int it = 0; it < D / 4 / 32; it++) {
            float4 xv = __ldg(xr + lane + 32 * it);
#pragma unroll
            for (int j = 0; j < H; j++) {
                float4 wv = __ldg(W14 + j * (D / 4) + lane + 32 * it);
                acc[j] += xv.x * wv.x + xv.y * wv.y + xv.z * wv.z + xv.w * wv.w;
            }
        }
#pragma unroll
        for (int j = 0; j < H; j++) {
#pragma unroll
            for (int off = 16; off; off >>= 1)
                acc[j] += __shfl_xor_sync(0xffffffffu, acc[j], off);
        }
        if (lane == 0) {
#pragma unroll
            for (int j = 0; j < H; j++) {
                float yv = acc[j] + __ldg(b1 + j);
                g_y[n * H + j] = yv;
                ls[j] += (double)yv;
                lq[j] += (double)yv * (double)yv;
            }
        }
    }
    if (lane == 0) {
#pragma unroll
        for (int j = 0; j < H; j++) {
            atomicAdd(&g_s1[j], ls[j]);
            atomicAdd(&g_sq1[j], lq[j]);
        }
    }
}

// ---------------- BN1 affine params + zero-cell bias (pre-scaled) ----------------
__global__ void k_bnparams(const float* __restrict__ g1, const float* __restrict__ be1,
                           const float* __restrict__ b_ih, const float* __restrict__ b_hh) {
    int t = threadIdx.x;
    if (t < H) {
        double m   = g_s1[t] / (double)NROWS;
        double var = g_sq1[t] / (double)NROWS - m * m;
        float inv  = (float)(1.0 / sqrt(var + 1e-5));
        float sc   = inv * __ldg(g1 + t);
        g_scale1[t] = sc;
        g_shift1[t] = __ldg(be1 + t) - (float)m * sc;
    }
    if (t < G4) {
        int gate = t / H;
        float s  = (gate == 2) ? 1.0f : 0.5f;
        g_bias0[t] = s * (__ldg(b_ih + t) + __ldg(b_hh + t));
    }
}

// ---------------- kernel B: u[n,r] = scale_r*(b + W_ih[r,:].x1[n,:]) + meta ----------------
__global__ void k_u(const float* __restrict__ W_ih,
                    const float* __restrict__ b_ih, const float* __restrict__ b_hh,
                    const int* __restrict__ zero_pad, const int* __restrict__ broad_id) {
    int tid = blockIdx.x * blockDim.x + threadIdx.x;
    if (tid >= NROWS * G4) return;
    int n = tid / G4;
    int r = tid % G4;
    float acc = __ldg(b_ih + r) + __ldg(b_hh + r);
#pragma unroll
    for (int j = 0; j < H; j++) {
        float x1 = g_y[n * H + j] * g_scale1[j] + g_shift1[j];
        acc += __ldg(W_ih + r * H + j) * x1;
    }
    if ((r / H) != 2) acc *= 0.5f;
    g_u[tid] = acc;
    if (r == 0) {
        int zp = __ldg(zero_pad + n);
        zp = min(max(zp, 0), 3);
        int bnd = (n == NROWS - 1) || (__ldg(broad_id + n + 1) != __ldg(broad_id + n));
        g_meta[n] = zp | (bnd << 8);
        if (n == 0) {
            g_meta[NROWS] = 0; g_meta[NROWS + 1] = 0;
#pragma unroll
            for (int q = 0; q < 2 * G4; q++) g_u[NROWS * G4 + q] = 0.f;
        }
    }
}

// ---------------- group starts (single block prefix over boundary flags) ----------------
#define RPT (NROWS / 1024)
__global__ void k_groups(const int* __restrict__ broad_id) {
    __shared__ int s[1024];
    int tid = threadIdx.x;
    int base = tid * RPT;
    // count group starts in my segment
    int cnt = 0;
#pragma unroll 8
    for (int i = 0; i < RPT; i++) {
        int n = base + i;
        int st = (n == 0) || (__ldg(broad_id + n) != __ldg(broad_id + n - 1));
        cnt += st;
    }
    s[tid] = cnt;
    __syncthreads();
    for (int off = 1; off < 1024; off <<= 1) {
        int v = (tid >= off) ? s[tid - off] : 0;
        __syncthreads();
        s[tid] += v;
        __syncthreads();
    }
    int gid = s[tid] - cnt;  // exclusive
#pragma unroll 8
    for (int i = 0; i < RPT; i++) {
        int n = base + i;
        int st = (n == 0) || (__ldg(broad_id + n) != __ldg(broad_id + n - 1));
        if (st) { g_gstart[gid] = n; gid++; }
    }
    if (tid == 1023) g_ngroups = s[1023];
}

// ---------------- scan math: hardware tanh ----------------
__device__ __forceinline__ float tanhapx(float x) {
    float y;
    asm("tanh.approx.f32 %0, %1;" : "=f"(y) : "f"(x));
    return y;
}
__device__ __forceinline__ float sig_h(float p) {   // p already halved
    return fmaf(tanhapx(p), 0.5f, 0.5f);
}

// ---------------- chunked scan: one warp per chunk, warm-up from zero state ----------------
__global__ void k_scan(const float* __restrict__ W_hh) {
    int j  = threadIdx.x;
    int lj = (j < H) ? j : 0;

    int ng  = g_ngroups;
    int gpc = (ng + NCHUNK - 1) / NCHUNK;
    int c   = blockIdx.x;
    int g0  = c * gpc;
    if (g0 >= ng) return;
    int g1  = min(g0 + gpc, ng);
    int gw  = max(g0 - WU, 0);

    int row_start    = g_gstart[gw];
    int region_start = g_gstart[g0];
    int row_end      = (g1 < ng) ? g_gstart[g1] : NROWS;

    // W_hh rows for this lane's 4 gates; 0.5 folded for sigmoid gates
    float wi[H], wf[H], wg[H], wo[H];
#pragma unroll
    for (int k = 0; k < H; k++) {
        wi[k] = 0.5f * __ldg(W_hh + (0 * H + lj) * H + k);
        wf[k] = 0.5f * __ldg(W_hh + (1 * H + lj) * H + k);
        wg[k] =        __ldg(W_hh + (2 * H + lj) * H + k);
        wo[k] = 0.5f * __ldg(W_hh + (3 * H + lj) * H + k);
    }
    float bz0 = g_bias0[0 * H + lj], bz1 = g_bias0[1 * H + lj];
    float bz2 = g_bias0[2 * H + lj], bz3 = g_bias0[3 * H + lj];

    float hv[H];
#pragma unroll
    for (int k = 0; k < H; k++) hv[k] = 0.f;
    float cstate = 0.f, sh = 0.f, sc = 0.f, cnt = 0.f;

    // prefetch first step
    int   m0 = g_meta[row_start];
    const float* u0 = g_u + (size_t)row_start * G4;
    float a0 = __ldg(u0 + 0 * H + lj);
    float a1 = __ldg(u0 + 1 * H + lj);
    float a2 = __ldg(u0 + 2 * H + lj);
    float a3 = __ldg(u0 + 3 * H + lj);

    for (int t = row_start; t < row_end; t++) {
        // prefetch next step (padded arrays: safe at t+1 == NROWS)
        const float* up = g_u + (size_t)(t + 1) * G4;
        int   m1 = g_meta[t + 1];
        float p0 = __ldg(up + 0 * H + lj);
        float p1 = __ldg(up + 1 * H + lj);
        float p2 = __ldg(up + 2 * H + lj);
        float p3 = __ldg(up + 3 * H + lj);

        int zp = m0 & 0xff;
        for (int k = 0; k < zp; k++) {
            float pi = bz0, pf = bz1, pg = bz2, po = bz3;
#pragma unroll
            for (int q = 0; q < H; q++) {
                pi += wi[q] * hv[q];
                pf += wf[q] * hv[q];
                pg += wg[q] * hv[q];
                po += wo[q] * hv[q];
            }
            float ig = sig_h(pi), fg = sig_h(pf), gg = tanhapx(pg), og = sig_h(po);
            cstate = fmaf(fg, cstate, ig * gg);
            float hn = og * tanhapx(cstate);
#pragma unroll
            for (int q = 0; q < H; q++) hv[q] = __shfl_sync(0xffffffffu, hn, q);
        }

        {   // input cell (does not advance carry)
            float pi = a0, pf = a1, pg = a2, po = a3;
#pragma unroll
            for (int q = 0; q < H; q++) {
                pi += wi[q] * hv[q];
                pf += wf[q] * hv[q];
                pg += wg[q] * hv[q];
                po += wo[q] * hv[q];
            }
            float ig = sig_h(pi), fg = sig_h(pf), gg = tanhapx(pg), og = sig_h(po);
            float ct = fmaf(fg, cstate, ig * gg);
            float ht = og * tanhapx(ct);

            if (t >= region_start && j < H) g_outs[t * H + j] = ht;
            sh += ht; sc += ct; cnt += 1.f;

            if (m0 & 0x100) {
                float invc = __fdividef(1.f, cnt);
                float hn   = sh * invc;
                cstate     = sc * invc;
                sh = 0.f; sc = 0.f; cnt = 0.f;
#pragma unroll
                for (int q = 0; q < H; q++) hv[q] = __shfl_sync(0xffffffffu, hn, q);
            }
        }

        m0 = m1; a0 = p0; a1 = p1; a2 = p2; a3 = p3;
    }
}

// ---------------- BN2 sums over g_outs ----------------
__global__ void k_stats() {
    int gtid  = blockIdx.x * blockDim.x + threadIdx.x;
    int w     = gtid >> 5;
    int lane  = threadIdx.x & 31;
    int nwarp = (gridDim.x * blockDim.x) >> 5;
    if (lane >= H) return;
    double s = 0.0, q = 0.0;
    for (int n = w; n < NROWS; n += nwarp) {
        double v = (double)g_outs[n * H + lane];
        s += v;
        q += v * v;
    }
    atomicAdd(&g_s2[lane], s);
    atomicAdd(&g_s2[H + lane], q);
}

// ---------------- fold BN2 + W2 + b2 ----------------
__global__ void k_post(const float* __restrict__ g2, const float* __restrict__ be2,
                       const float* __restrict__ W2, const float* __restrict__ b2) {
    if (threadIdx.x == 0) {
        float cst = __ldg(b2);
#pragma unroll
        for (int jj = 0; jj < H; jj++) {
            double m   = g_s2[jj] / (double)NROWS;
            double var = g_s2[H + jj] / (double)NROWS - m * m;
            float inv  = (float)(1.0 / sqrt(var + 1e-5));
            float a    = __ldg(W2 + jj) * __ldg(g2 + jj) * inv;
            g_alpha[jj] = a;
            cst += __ldg(W2 + jj) * __ldg(be2 + jj) - (float)m * a;
        }
        g_cst[0] = cst;
    }
}

// ---------------- out = tanh(outs . alpha + cst) ----------------
__global__ void k_final(float* __restrict__ out) {
    int n = blockIdx.x * blockDim.x + threadIdx.x;
    if (n >= NROWS) return;
    float acc = g_cst[0];
#pragma unroll
    for (int jj = 0; jj < H; jj++)
        acc += g_outs[n * H + jj] * g_alpha[jj];
    out[n] = tanhf(acc);
}

// ---------------- launch ----------------
extern "C" void kernel_launch(void* const* d_in, const int* in_sizes, int n_in,
                              void* d_out, int out_size) {
    const float* x        = (const float*)d_in[0];
    const int*   zero_pad = (const int*)d_in[1];
    const int*   broad_id = (const int*)d_in[2];
    const float* W1       = (const float*)d_in[3];
    const float* b1       = (const float*)d_in[4];
    const float* g1       = (const float*)d_in[5];
    const float* be1      = (const float*)d_in[6];
    const float* W_ih     = (const float*)d_in[7];
    const float* W_hh     = (const float*)d_in[8];
    const float* b_ih     = (const float*)d_in[9];
    const float* b_hh     = (const float*)d_in[10];
    const float* g2       = (const float*)d_in[11];
    const float* be2      = (const float*)d_in[12];
    const float* W2       = (const float*)d_in[13];
    const float* b2       = (const float*)d_in[14];
    float* out = (float*)d_out;

    k_init<<<1, 32>>>();
    k_proj<<<512, 256>>>(x, W1, b1);
    k_bnparams<<<1, 64>>>(g1, be1, b_ih, b_hh);
    k_u<<<(NROWS * G4) / 256, 256>>>(W_ih, b_ih, b_hh, zero_pad, broad_id);
    k_groups<<<1, 1024>>>(broad_id);
    k_scan<<<NCHUNK, 32>>>(W_hh);
    k_stats<<<128, 256>>>();
    k_post<<<1, 32>>>(g2, be2, W2, b2);
    k_final<<<NROWS / 256, 256>>>(out);
}

// round 5
// speedup vs baseline: 72.5950x; 1.3009x over previous
#include <cuda_runtime.h>
#include <math.h>

#define NROWS 65536
#define D 512
#define H 10
#define G4 40
#define MAXID 8192
#define NCHUNK 1024
#define IPC (MAXID / NCHUNK)    // ids per chunk = 8
#define WUIDS 8                 // warm-up ids per chunk
#define PBLK 1024               // k_proj grid

// ---------------- scratch (static device globals; no allocation) ----------------
__device__ float  g_y[NROWS * H];                   // layer-1 pre-BN activations
__device__ __align__(16) float g_u[(NROWS + 2) * G4];
__device__ float  g_outs[NROWS * H];
__device__ int    g_meta[NROWS + 2];                // zp | (bnd<<8)
__device__ int    g_idstart[MAXID + 1];             // first row with id >= v
__device__ float  g_part1[PBLK * 2 * H];            // per-block BN1 partials
__device__ float  g_scale1[H], g_shift1[H];
__device__ float  g_bias0[G4];                      // 0.5*(b_ih+b_hh) for i,f,o ; 1.0* for g
__device__ double g_s2[2 * H];                      // BN2 sums
__device__ float  g_alpha[H];
__device__ float  g_cst[1];

// ---------------- kernel A: y = x @ W1^T + b1, per-block BN1 partials ----------------
// warp-pair per row-stream: each warp owns 5 of the 10 output columns, W in registers
__global__ void k_proj(const float* __restrict__ x,
                       const float* __restrict__ W1,
                       const float* __restrict__ b1) {
    int w    = threadIdx.x >> 5;
    int lane = threadIdx.x & 31;
    int gw   = blockIdx.x * 8 + w;
    int pair = gw >> 1;
    int jh   = (gw & 1) * 5;          // column offset: 0 or 5
    const int NPAIR = PBLK * 4;

    const float4* x4  = reinterpret_cast<const float4*>(x);
    const float4* W14 = reinterpret_cast<const float4*>(W1);

    float4 wreg[5][4];
#pragma unroll
    for (int jj = 0; jj < 5; jj++)
#pragma unroll
        for (int it = 0; it < 4; it++)
            wreg[jj][it] = __ldg(W14 + (jh + jj) * (D / 4) + it * 32 + lane);

    float bb[5];
#pragma unroll
    for (int jj = 0; jj < 5; jj++) bb[jj] = __ldg(b1 + jh + jj);

    float ls[5], lq[5];
#pragma unroll
    for (int jj = 0; jj < 5; jj++) { ls[jj] = 0.f; lq[jj] = 0.f; }

    for (int n = pair; n < NROWS; n += NPAIR) {
        float acc[5];
#pragma unroll
        for (int jj = 0; jj < 5; jj++) acc[jj] = 0.f;
        const float4* xr = x4 + (size_t)n * (D / 4);
#pragma unroll
        for (int it = 0; it < 4; it++) {
            float4 xv = __ldg(xr + it * 32 + lane);
#pragma unroll
            for (int jj = 0; jj < 5; jj++) {
                float4 wv = wreg[jj][it];
                acc[jj] += xv.x * wv.x + xv.y * wv.y + xv.z * wv.z + xv.w * wv.w;
            }
        }
#pragma unroll
        for (int jj = 0; jj < 5; jj++) {
#pragma unroll
            for (int off = 16; off; off >>= 1)
                acc[jj] += __shfl_xor_sync(0xffffffffu, acc[jj], off);
        }
        if (lane == 0) {
#pragma unroll
            for (int jj = 0; jj < 5; jj++) {
                float yv = acc[jj] + bb[jj];
                g_y[n * H + jh + jj] = yv;
                ls[jj] += yv;
                lq[jj] += yv * yv;
            }
        }
    }

    __shared__ float ss[8][H], sq[8][H];
    if (lane < H) { ss[w][lane] = 0.f; sq[w][lane] = 0.f; }
    __syncthreads();
    if (lane == 0) {
#pragma unroll
        for (int jj = 0; jj < 5; jj++) { ss[w][jh + jj] = ls[jj]; sq[w][jh + jj] = lq[jj]; }
    }
    __syncthreads();
    int t = threadIdx.x;
    if (t < H) {
        float a = 0.f, b = 0.f;
#pragma unroll
        for (int ww = 0; ww < 8; ww++) { a += ss[ww][t]; b += sq[ww][t]; }
        g_part1[blockIdx.x * 2 * H + t]     = a;
        g_part1[blockIdx.x * 2 * H + H + t] = b;
    }
}

// ---------------- BN1 params + zero-cell bias + zero BN2 sums ----------------
__global__ void k_bnparams(const float* __restrict__ g1, const float* __restrict__ be1,
                           const float* __restrict__ b_ih, const float* __restrict__ b_hh) {
    int t = threadIdx.x;
    if (t < H) {
        double s = 0.0, q = 0.0;
        for (int b = 0; b < PBLK; b++) {
            s += (double)g_part1[b * 2 * H + t];
            q += (double)g_part1[b * 2 * H + H + t];
        }
        double m   = s / (double)NROWS;
        double var = q / (double)NROWS - m * m;
        float inv  = (float)(1.0 / sqrt(var + 1e-5));
        float sc   = inv * __ldg(g1 + t);
        g_scale1[t] = sc;
        g_shift1[t] = __ldg(be1 + t) - (float)m * sc;
    }
    if (t < 2 * H) g_s2[t] = 0.0;
    if (t < G4) {
        int gate = t / H;
        float s  = (gate == 2) ? 1.0f : 0.5f;
        g_bias0[t] = s * (__ldg(b_ih + t) + __ldg(b_hh + t));
    }
}

// ---------------- kernel B: one thread per row -> u[40], meta, idstart scatter ----------------
__global__ void k_u(const float* __restrict__ W_ih,
                    const float* __restrict__ b_ih, const float* __restrict__ b_hh,
                    const int* __restrict__ zero_pad, const int* __restrict__ broad_id) {
    __shared__ float sW[G4 * H], sb[G4], ssc[H], ssh[H];
    for (int i = threadIdx.x; i < G4 * H; i += blockDim.x) sW[i] = __ldg(W_ih + i);
    for (int i = threadIdx.x; i < G4; i += blockDim.x)
        sb[i] = __ldg(b_ih + i) + __ldg(b_hh + i);
    if (threadIdx.x < H) { ssc[threadIdx.x] = g_scale1[threadIdx.x]; ssh[threadIdx.x] = g_shift1[threadIdx.x]; }
    __syncthreads();

    int n = blockIdx.x * blockDim.x + threadIdx.x;
    if (n >= NROWS) return;

    float x1[H];
#pragma unroll
    for (int j = 0; j < H; j++)
        x1[j] = g_y[n * H + j] * ssc[j] + ssh[j];

    float u[G4];
#pragma unroll
    for (int r = 0; r < G4; r++) {
        float acc = sb[r];
#pragma unroll
        for (int j = 0; j < H; j++) acc += sW[r * H + j] * x1[j];
        if ((r / H) != 2) acc *= 0.5f;     // fold sigmoid's x/2 for i,f,o
        u[r] = acc;
    }
    float4* u4 = reinterpret_cast<float4*>(g_u + (size_t)n * G4);
#pragma unroll
    for (int i = 0; i < 10; i++)
        u4[i] = make_float4(u[4 * i], u[4 * i + 1], u[4 * i + 2], u[4 * i + 3]);

    int idc = __ldg(broad_id + n);
    int idp = (n > 0) ? __ldg(broad_id + n - 1) : -1;
    for (int v = idp + 1; v <= idc; v++) g_idstart[v] = n;    // gaps -> next row
    if (n == NROWS - 1)
        for (int v = idc + 1; v <= MAXID; v++) g_idstart[v] = NROWS;

    int zp = __ldg(zero_pad + n);
    zp = min(max(zp, 0), 3);
    int bnd = (n == NROWS - 1) || (__ldg(broad_id + n + 1) != idc);
    g_meta[n] = zp | (bnd << 8);
}

// ---------------- scan math: hardware tanh ----------------
__device__ __forceinline__ float tanhapx(float x) {
    float y;
    asm("tanh.approx.f32 %0, %1;" : "=f"(y) : "f"(x));
    return y;
}
__device__ __forceinline__ float sig_h(float p) {   // p already halved
    return fmaf(tanhapx(p), 0.5f, 0.5f);
}

// ---------------- chunked scan: one warp per id-range chunk ----------------
__global__ void k_scan(const float* __restrict__ W_hh) {
    int j  = threadIdx.x;
    int lj = (j < H) ? j : 0;

    int lo  = blockIdx.x * IPC;
    int wlo = max(lo - WUIDS, 0);
    int row_start    = g_idstart[wlo];
    int region_start = g_idstart[lo];
    int row_end      = g_idstart[lo + IPC];
    if (region_start >= row_end) return;

    float wi[H], wf[H], wg[H], wo[H];
#pragma unroll
    for (int k = 0; k < H; k++) {
        wi[k] = 0.5f * __ldg(W_hh + (0 * H + lj) * H + k);
        wf[k] = 0.5f * __ldg(W_hh + (1 * H + lj) * H + k);
        wg[k] =        __ldg(W_hh + (2 * H + lj) * H + k);
        wo[k] = 0.5f * __ldg(W_hh + (3 * H + lj) * H + k);
    }
    float bz0 = g_bias0[0 * H + lj], bz1 = g_bias0[1 * H + lj];
    float bz2 = g_bias0[2 * H + lj], bz3 = g_bias0[3 * H + lj];

    float hv[H];
#pragma unroll
    for (int k = 0; k < H; k++) hv[k] = 0.f;
    float cstate = 0.f, sh = 0.f, sc = 0.f, cnt = 0.f;

    int   m0 = g_meta[row_start];
    const float* u0 = g_u + (size_t)row_start * G4;
    float a0 = __ldg(u0 + 0 * H + lj);
    float a1 = __ldg(u0 + 1 * H + lj);
    float a2 = __ldg(u0 + 2 * H + lj);
    float a3 = __ldg(u0 + 3 * H + lj);

    for (int t = row_start; t < row_end; t++) {
        const float* up = g_u + (size_t)(t + 1) * G4;
        int   m1 = g_meta[t + 1];
        float p0 = __ldg(up + 0 * H + lj);
        float p1 = __ldg(up + 1 * H + lj);
        float p2 = __ldg(up + 2 * H + lj);
        float p3 = __ldg(up + 3 * H + lj);

        int zp = m0 & 0xff;
        for (int k = 0; k < zp; k++) {
            float pi = bz0, pf = bz1, pg = bz2, po = bz3;
#pragma unroll
            for (int q = 0; q < H; q++) {
                pi += wi[q] * hv[q];
                pf += wf[q] * hv[q];
                pg += wg[q] * hv[q];
                po += wo[q] * hv[q];
            }
            float ig = sig_h(pi), fg = sig_h(pf), gg = tanhapx(pg), og = sig_h(po);
            cstate = fmaf(fg, cstate, ig * gg);
            float hn = og * tanhapx(cstate);
#pragma unroll
            for (int q = 0; q < H; q++) hv[q] = __shfl_sync(0xffffffffu, hn, q);
        }

        {   // input cell (does not advance carry)
            float pi = a0, pf = a1, pg = a2, po = a3;
#pragma unroll
            for (int q = 0; q < H; q++) {
                pi += wi[q] * hv[q];
                pf += wf[q] * hv[q];
                pg += wg[q] * hv[q];
                po += wo[q] * hv[q];
            }
            float ig = sig_h(pi), fg = sig_h(pf), gg = tanhapx(pg), og = sig_h(po);
            float ct = fmaf(fg, cstate, ig * gg);
            float ht = og * tanhapx(ct);

            if (t >= region_start && j < H) g_outs[t * H + j] = ht;
            sh += ht; sc += ct; cnt += 1.f;

            if (m0 & 0x100) {
                float invc = __fdividef(1.f, cnt);
                float hn   = sh * invc;
                cstate     = sc * invc;
                sh = 0.f; sc = 0.f; cnt = 0.f;
#pragma unroll
                for (int q = 0; q < H; q++) hv[q] = __shfl_sync(0xffffffffu, hn, q);
            }
        }

        m0 = m1; a0 = p0; a1 = p1; a2 = p2; a3 = p3;
    }
}

// ---------------- BN2 sums over g_outs ----------------
__global__ void k_stats() {
    int gtid  = blockIdx.x * blockDim.x + threadIdx.x;
    int w     = gtid >> 5;
    int lane  = threadIdx.x & 31;
    int nwarp = (gridDim.x * blockDim.x) >> 5;
    if (lane >= H) return;
    double s = 0.0, q = 0.0;
    for (int n = w; n < NROWS; n += nwarp) {
        double v = (double)g_outs[n * H + lane];
        s += v;
        q += v * v;
    }
    atomicAdd(&g_s2[lane], s);
    atomicAdd(&g_s2[H + lane], q);
}

// ---------------- fold BN2 + W2 + b2 ----------------
__global__ void k_post(const float* __restrict__ g2, const float* __restrict__ be2,
                       const float* __restrict__ W2, const float* __restrict__ b2) {
    if (threadIdx.x == 0) {
        float cst = __ldg(b2);
#pragma unroll
        for (int jj = 0; jj < H; jj++) {
            double m   = g_s2[jj] / (double)NROWS;
            double var = g_s2[H + jj] / (double)NROWS - m * m;
            float inv  = (float)(1.0 / sqrt(var + 1e-5));
            float a    = __ldg(W2 + jj) * __ldg(g2 + jj) * inv;
            g_alpha[jj] = a;
            cst += __ldg(W2 + jj) * __ldg(be2 + jj) - (float)m * a;
        }
        g_cst[0] = cst;
    }
}

// ---------------- out = tanh(outs . alpha + cst) ----------------
__global__ void k_final(float* __restrict__ out) {
    int n = blockIdx.x * blockDim.x + threadIdx.x;
    if (n >= NROWS) return;
    float acc = g_cst[0];
#pragma unroll
    for (int jj = 0; jj < H; jj++)
        acc += g_outs[n * H + jj] * g_alpha[jj];
    out[n] = tanhf(acc);
}

// ---------------- launch ----------------
extern "C" void kernel_launch(void* const* d_in, const int* in_sizes, int n_in,
                              void* d_out, int out_size) {
    const float* x        = (const float*)d_in[0];
    const int*   zero_pad = (const int*)d_in[1];
    const int*   broad_id = (const int*)d_in[2];
    const float* W1       = (const float*)d_in[3];
    const float* b1       = (const float*)d_in[4];
    const float* g1       = (const float*)d_in[5];
    const float* be1      = (const float*)d_in[6];
    const float* W_ih     = (const float*)d_in[7];
    const float* W_hh     = (const float*)d_in[8];
    const float* b_ih     = (const float*)d_in[9];
    const float* b_hh     = (const float*)d_in[10];
    const float* g2       = (const float*)d_in[11];
    const float* be2      = (const float*)d_in[12];
    const float* W2       = (const float*)d_in[13];
    const float* b2       = (const float*)d_in[14];
    float* out = (float*)d_out;

    k_proj<<<PBLK, 256>>>(x, W1, b1);
    k_bnparams<<<1, 64>>>(g1, be1, b_ih, b_hh);
    k_u<<<NROWS / 256, 256>>>(W_ih, b_ih, b_hh, zero_pad, broad_id);
    k_scan<<<NCHUNK, 32>>>(W_hh);
    k_stats<<<128, 256>>>();
    k_post<<<1, 32>>>(g2, be2, W2, b2);
    k_final<<<NROWS / 256, 256>>>(out);
}

// round 6
// speedup vs baseline: 171.1378x; 2.3574x over previous
#include <cuda_runtime.h>
#include <math.h>

#define NROWS 65536
#define D 512
#define H 10
#define G4 40
#define MAXID 8192
#define NCHUNK 2048
#define IPC (MAXID / NCHUNK)    // ids per chunk = 4
#define WUIDS 4                 // warm-up ids per chunk
#define PBLK 1024               // k_proj grid

// ---------------- scratch (static device globals; no allocation) ----------------
__device__ float  g_y[NROWS * H];                   // layer-1 pre-BN activations
__device__ __align__(16) float g_u[(NROWS + 2) * G4];
__device__ float  g_outs[NROWS * H];
__device__ int    g_meta[NROWS + 2];                // zp | (bnd<<8)
__device__ int    g_idstart[MAXID + 1];             // first row with id >= v
__device__ float  g_part1[PBLK * 2 * H];            // per-block BN1 partials
__device__ float  g_scale1[H], g_shift1[H];
__device__ float  g_bias0[G4];                      // 0.5*(b_ih+b_hh) for i,f,o ; 1.0* for g
__device__ double g_s2[2 * H];                      // BN2 sums (scan-fused atomics)
__device__ float  g_alpha[H];
__device__ float  g_cst[1];

// ---------------- kernel A: y = x @ W1^T + b1, per-block BN1 partials ----------------
__global__ void k_proj(const float* __restrict__ x,
                       const float* __restrict__ W1,
                       const float* __restrict__ b1) {
    int w    = threadIdx.x >> 5;
    int lane = threadIdx.x & 31;
    int gw   = blockIdx.x * 8 + w;
    int pair = gw >> 1;
    int jh   = (gw & 1) * 5;          // column offset: 0 or 5
    const int NPAIR = PBLK * 4;

    const float4* x4  = reinterpret_cast<const float4*>(x);
    const float4* W14 = reinterpret_cast<const float4*>(W1);

    float4 wreg[5][4];
#pragma unroll
    for (int jj = 0; jj < 5; jj++)
#pragma unroll
        for (int it = 0; it < 4; it++)
            wreg[jj][it] = __ldg(W14 + (jh + jj) * (D / 4) + it * 32 + lane);

    float bb[5];
#pragma unroll
    for (int jj = 0; jj < 5; jj++) bb[jj] = __ldg(b1 + jh + jj);

    float ls[5], lq[5];
#pragma unroll
    for (int jj = 0; jj < 5; jj++) { ls[jj] = 0.f; lq[jj] = 0.f; }

    for (int n = pair; n < NROWS; n += NPAIR) {
        float acc[5];
#pragma unroll
        for (int jj = 0; jj < 5; jj++) acc[jj] = 0.f;
        const float4* xr = x4 + (size_t)n * (D / 4);
#pragma unroll
        for (int it = 0; it < 4; it++) {
            float4 xv = __ldg(xr + it * 32 + lane);
#pragma unroll
            for (int jj = 0; jj < 5; jj++) {
                float4 wv = wreg[jj][it];
                acc[jj] += xv.x * wv.x + xv.y * wv.y + xv.z * wv.z + xv.w * wv.w;
            }
        }
#pragma unroll
        for (int jj = 0; jj < 5; jj++) {
#pragma unroll
            for (int off = 16; off; off >>= 1)
                acc[jj] += __shfl_xor_sync(0xffffffffu, acc[jj], off);
        }
        if (lane == 0) {
#pragma unroll
            for (int jj = 0; jj < 5; jj++) {
                float yv = acc[jj] + bb[jj];
                g_y[n * H + jh + jj] = yv;
                ls[jj] += yv;
                lq[jj] += yv * yv;
            }
        }
    }

    __shared__ float ss[8][H], sq[8][H];
    if (lane < H) { ss[w][lane] = 0.f; sq[w][lane] = 0.f; }
    __syncthreads();
    if (lane == 0) {
#pragma unroll
        for (int jj = 0; jj < 5; jj++) { ss[w][jh + jj] = ls[jj]; sq[w][jh + jj] = lq[jj]; }
    }
    __syncthreads();
    int t = threadIdx.x;
    if (t < H) {
        float a = 0.f, b = 0.f;
#pragma unroll
        for (int ww = 0; ww < 8; ww++) { a += ss[ww][t]; b += sq[ww][t]; }
        g_part1[blockIdx.x * 2 * H + t]     = a;
        g_part1[blockIdx.x * 2 * H + H + t] = b;
    }
}

// ---------------- BN1 params: parallel tree reduction over PBLK partials ----------------
// 640 threads: col = tid/32 (0..19), lane strides over blocks
__global__ void k_bnred(const float* __restrict__ g1, const float* __restrict__ be1,
                        const float* __restrict__ b_ih, const float* __restrict__ b_hh) {
    __shared__ float red[2 * H];
    int tid  = threadIdx.x;
    int col  = tid >> 5;        // 0..19
    int lane = tid & 31;
    if (col < 2 * H) {
        float s = 0.f;
        for (int b = lane; b < PBLK; b += 32)
            s += g_part1[b * 2 * H + col];
#pragma unroll
        for (int off = 16; off; off >>= 1)
            s += __shfl_xor_sync(0xffffffffu, s, off);
        if (lane == 0) red[col] = s;
    }
    __syncthreads();
    if (tid < H) {
        double m   = (double)red[tid] / (double)NROWS;
        double var = (double)red[H + tid] / (double)NROWS - m * m;
        float inv  = (float)(1.0 / sqrt(var + 1e-5));
        float sc   = inv * __ldg(g1 + tid);
        g_scale1[tid] = sc;
        g_shift1[tid] = __ldg(be1 + tid) - (float)m * sc;
    }
    if (tid < 2 * H) g_s2[tid] = 0.0;
    if (tid < G4) {
        int gate = tid / H;
        float s  = (gate == 2) ? 1.0f : 0.5f;
        g_bias0[tid] = s * (__ldg(b_ih + tid) + __ldg(b_hh + tid));
    }
}

// ---------------- kernel B: one thread per row -> u[40], meta, idstart scatter ----------------
__global__ void k_u(const float* __restrict__ W_ih,
                    const float* __restrict__ b_ih, const float* __restrict__ b_hh,
                    const int* __restrict__ zero_pad, const int* __restrict__ broad_id) {
    __shared__ float sW[G4 * H], sb[G4], ssc[H], ssh[H];
    for (int i = threadIdx.x; i < G4 * H; i += blockDim.x) sW[i] = __ldg(W_ih + i);
    for (int i = threadIdx.x; i < G4; i += blockDim.x)
        sb[i] = __ldg(b_ih + i) + __ldg(b_hh + i);
    if (threadIdx.x < H) { ssc[threadIdx.x] = g_scale1[threadIdx.x]; ssh[threadIdx.x] = g_shift1[threadIdx.x]; }
    __syncthreads();

    int n = blockIdx.x * blockDim.x + threadIdx.x;
    if (n >= NROWS) return;

    float x1[H];
#pragma unroll
    for (int j = 0; j < H; j++)
        x1[j] = g_y[n * H + j] * ssc[j] + ssh[j];

    float u[G4];
#pragma unroll
    for (int r = 0; r < G4; r++) {
        float acc = sb[r];
#pragma unroll
        for (int j = 0; j < H; j++) acc += sW[r * H + j] * x1[j];
        if ((r / H) != 2) acc *= 0.5f;     // fold sigmoid's x/2 for i,f,o
        u[r] = acc;
    }
    float4* u4 = reinterpret_cast<float4*>(g_u + (size_t)n * G4);
#pragma unroll
    for (int i = 0; i < 10; i++)
        u4[i] = make_float4(u[4 * i], u[4 * i + 1], u[4 * i + 2], u[4 * i + 3]);

    int idc = __ldg(broad_id + n);
    int idp = (n > 0) ? __ldg(broad_id + n - 1) : -1;
    for (int v = idp + 1; v <= idc; v++) g_idstart[v] = n;    // gaps -> next row
    if (n == NROWS - 1)
        for (int v = idc + 1; v <= MAXID; v++) g_idstart[v] = NROWS;

    int zp = __ldg(zero_pad + n);
    zp = min(max(zp, 0), 3);
    int bnd = (n == NROWS - 1) || (__ldg(broad_id + n + 1) != idc);
    g_meta[n] = zp | (bnd << 8);
}

// ---------------- scan math: hardware tanh ----------------
__device__ __forceinline__ float tanhapx(float x) {
    float y;
    asm("tanh.approx.f32 %0, %1;" : "=f"(y) : "f"(x));
    return y;
}
__device__ __forceinline__ float sig_h(float p) {   // p already halved
    return fmaf(tanhapx(p), 0.5f, 0.5f);
}

// ---------------- chunked scan: one warp per id-range chunk; BN2 stats fused ----------------
__global__ void k_scan(const float* __restrict__ W_hh) {
    int j  = threadIdx.x;
    int lj = (j < H) ? j : 0;

    int lo  = blockIdx.x * IPC;
    int wlo = max(lo - WUIDS, 0);
    int row_start    = g_idstart[wlo];
    int region_start = g_idstart[lo];
    int row_end      = g_idstart[lo + IPC];
    if (region_start >= row_end) return;

    float wi[H], wf[H], wg[H], wo[H];
#pragma unroll
    for (int k = 0; k < H; k++) {
        wi[k] = 0.5f * __ldg(W_hh + (0 * H + lj) * H + k);
        wf[k] = 0.5f * __ldg(W_hh + (1 * H + lj) * H + k);
        wg[k] =        __ldg(W_hh + (2 * H + lj) * H + k);
        wo[k] = 0.5f * __ldg(W_hh + (3 * H + lj) * H + k);
    }
    float bz0 = g_bias0[0 * H + lj], bz1 = g_bias0[1 * H + lj];
    float bz2 = g_bias0[2 * H + lj], bz3 = g_bias0[3 * H + lj];

    float hv[H];
#pragma unroll
    for (int k = 0; k < H; k++) hv[k] = 0.f;
    float cstate = 0.f, sh = 0.f, sc = 0.f, cnt = 0.f;
    float st1 = 0.f, st2 = 0.f;     // fused BN2 partials (region rows only)

    int   m0 = g_meta[row_start];
    const float* u0 = g_u + (size_t)row_start * G4;
    float a0 = __ldg(u0 + 0 * H + lj);
    float a1 = __ldg(u0 + 1 * H + lj);
    float a2 = __ldg(u0 + 2 * H + lj);
    float a3 = __ldg(u0 + 3 * H + lj);

    for (int t = row_start; t < row_end; t++) {
        const float* up = g_u + (size_t)(t + 1) * G4;
        int   m1 = g_meta[t + 1];
        float p0 = __ldg(up + 0 * H + lj);
        float p1 = __ldg(up + 1 * H + lj);
        float p2 = __ldg(up + 2 * H + lj);
        float p3 = __ldg(up + 3 * H + lj);

        int zp = m0 & 0xff;
        for (int k = 0; k < zp; k++) {
            float pi = bz0, pf = bz1, pg = bz2, po = bz3;
#pragma unroll
            for (int q = 0; q < H; q++) {
                pi += wi[q] * hv[q];
                pf += wf[q] * hv[q];
                pg += wg[q] * hv[q];
                po += wo[q] * hv[q];
            }
            float ig = sig_h(pi), fg = sig_h(pf), gg = tanhapx(pg), og = sig_h(po);
            cstate = fmaf(fg, cstate, ig * gg);
            float hn = og * tanhapx(cstate);
#pragma unroll
            for (int q = 0; q < H; q++) hv[q] = __shfl_sync(0xffffffffu, hn, q);
        }

        {   // input cell (does not advance carry)
            float pi = a0, pf = a1, pg = a2, po = a3;
#pragma unroll
            for (int q = 0; q < H; q++) {
                pi += wi[q] * hv[q];
                pf += wf[q] * hv[q];
                pg += wg[q] * hv[q];
                po += wo[q] * hv[q];
            }
            float ig = sig_h(pi), fg = sig_h(pf), gg = tanhapx(pg), og = sig_h(po);
            float ct = fmaf(fg, cstate, ig * gg);
            float ht = og * tanhapx(ct);

            if (t >= region_start) {
                if (j < H) g_outs[t * H + j] = ht;
                st1 += ht;
                st2 = fmaf(ht, ht, st2);
            }
            sh += ht; sc += ct; cnt += 1.f;

            if (m0 & 0x100) {
                float invc = __fdividef(1.f, cnt);
                float hn   = sh * invc;
                cstate     = sc * invc;
                sh = 0.f; sc = 0.f; cnt = 0.f;
#pragma unroll
                for (int q = 0; q < H; q++) hv[q] = __shfl_sync(0xffffffffu, hn, q);
            }
        }

        m0 = m1; a0 = p0; a1 = p1; a2 = p2; a3 = p3;
    }

    if (j < H) {
        atomicAdd(&g_s2[j],     (double)st1);
        atomicAdd(&g_s2[H + j], (double)st2);
    }
}

// ---------------- fold BN2 + W2 + b2 ----------------
__global__ void k_post(const float* __restrict__ g2, const float* __restrict__ be2,
                       const float* __restrict__ W2, const float* __restrict__ b2) {
    if (threadIdx.x == 0) {
        float cst = __ldg(b2);
#pragma unroll
        for (int jj = 0; jj < H; jj++) {
            double m   = g_s2[jj] / (double)NROWS;
            double var = g_s2[H + jj] / (double)NROWS - m * m;
            float inv  = (float)(1.0 / sqrt(var + 1e-5));
            float a    = __ldg(W2 + jj) * __ldg(g2 + jj) * inv;
            g_alpha[jj] = a;
            cst += __ldg(W2 + jj) * __ldg(be2 + jj) - (float)m * a;
        }
        g_cst[0] = cst;
    }
}

// ---------------- out = tanh(outs . alpha + cst) ----------------
__global__ void k_final(float* __restrict__ out) {
    int n = blockIdx.x * blockDim.x + threadIdx.x;
    if (n >= NROWS) return;
    float acc = g_cst[0];
#pragma unroll
    for (int jj = 0; jj < H; jj++)
        acc += g_outs[n * H + jj] * g_alpha[jj];
    out[n] = tanhf(acc);
}

// ---------------- launch ----------------
extern "C" void kernel_launch(void* const* d_in, const int* in_sizes, int n_in,
                              void* d_out, int out_size) {
    const float* x        = (const float*)d_in[0];
    const int*   zero_pad = (const int*)d_in[1];
    const int*   broad_id = (const int*)d_in[2];
    const float* W1       = (const float*)d_in[3];
    const float* b1       = (const float*)d_in[4];
    const float* g1       = (const float*)d_in[5];
    const float* be1      = (const float*)d_in[6];
    const float* W_ih     = (const float*)d_in[7];
    const float* W_hh     = (const float*)d_in[8];
    const float* b_ih     = (const float*)d_in[9];
    const float* b_hh     = (const float*)d_in[10];
    const float* g2       = (const float*)d_in[11];
    const float* be2      = (const float*)d_in[12];
    const float* W2       = (const float*)d_in[13];
    const float* b2       = (const float*)d_in[14];
    float* out = (float*)d_out;

    k_proj<<<PBLK, 256>>>(x, W1, b1);
    k_bnred<<<1, 640>>>(g1, be1, b_ih, b_hh);
    k_u<<<NROWS / 256, 256>>>(W_ih, b_ih, b_hh, zero_pad, broad_id);
    k_scan<<<NCHUNK, 32>>>(W_hh);
    k_post<<<1, 32>>>(g2, be2, W2, b2);
    k_final<<<NROWS / 256, 256>>>(out);
}